// round 2
// baseline (speedup 1.0000x reference)
#include <cuda_runtime.h>

#define KS     5
#define TAPS   25      // KS*KS
#define CCH    3
#define HALO   2
#define TILE_W 32
#define TILE_H 8
#define SM_W   (TILE_W + 2*HALO)   // 36
#define SM_H   (TILE_H + 2*HALO)   // 12
#define NTHREADS 256

__global__ void __launch_bounds__(NTHREADS)
ho_fused_kernel(const float* __restrict__ x,
                const float* __restrict__ cw,   // [25][3][5][5] = [k][c][m]
                const float* __restrict__ cb,   // [25]
                float* __restrict__ out,
                int H, int W)
{
    __shared__ float s_tile[CCH][SM_H][SM_W];      // 1296 floats
    __shared__ float s_w[TAPS * CCH * TAPS];       // 1875 floats, [k][c][m]
    __shared__ float s_b[TAPS];

    const int tid = threadIdx.x;

    // Stage weights + bias into shared memory (warp-uniform broadcast reads later)
    for (int i = tid; i < TAPS * CCH * TAPS; i += NTHREADS) s_w[i] = cw[i];
    if (tid < TAPS) s_b[tid] = cb[tid];

    const int b  = blockIdx.z;
    const int h0 = blockIdx.y * TILE_H;
    const int w0 = blockIdx.x * TILE_W;
    const float* xb = x + (size_t)b * CCH * H * W;

    // Stage input tile with halo (zero-padded at image borders)
    for (int i = tid; i < CCH * SM_H * SM_W; i += NTHREADS) {
        int c   = i / (SM_H * SM_W);
        int r   = (i / SM_W) % SM_H;
        int col = i % SM_W;
        int hh = h0 + r   - HALO;
        int ww = w0 + col - HALO;
        float v = 0.0f;
        if (hh >= 0 && hh < H && ww >= 0 && ww < W)
            v = xb[(size_t)c * H * W + (size_t)hh * W + ww];
        s_tile[c][r][col] = v;
    }
    __syncthreads();

    const int tx = tid % TILE_W;
    const int ty = tid / TILE_W;

    // -------- Pass 1: per-pixel dynamic weights w_k = b_k + sum_{c,m} cw[k][c][m]*n[c][m]
    float wacc[TAPS];
#pragma unroll
    for (int k = 0; k < TAPS; k++) wacc[k] = s_b[k];

#pragma unroll
    for (int c = 0; c < CCH; c++) {
        float n[TAPS];
#pragma unroll
        for (int i = 0; i < KS; i++)
#pragma unroll
            for (int j = 0; j < KS; j++)
                n[i * KS + j] = s_tile[c][ty + i][tx + j];

#pragma unroll
        for (int k = 0; k < TAPS; k++) {
            const float* wk = &s_w[(k * CCH + c) * TAPS];
#pragma unroll
            for (int m = 0; m < TAPS; m++)
                wacc[k] += wk[m] * n[m];     // LDS (broadcast) + FFMA
        }
    }

    // -------- Pass 2: out[c] = x[c] + sum_m w_m * n[c][m]   (residual folded in)
    float* ob = out + (size_t)b * CCH * H * W;
    const int h = h0 + ty;
    const int w = w0 + tx;

#pragma unroll
    for (int c = 0; c < CCH; c++) {
        float acc = s_tile[c][ty + HALO][tx + HALO];   // residual x
#pragma unroll
        for (int i = 0; i < KS; i++)
#pragma unroll
            for (int j = 0; j < KS; j++)
                acc += wacc[i * KS + j] * s_tile[c][ty + i][tx + j];
        ob[(size_t)c * H * W + (size_t)h * W + w] = acc;
    }
}

extern "C" void kernel_launch(void* const* d_in, const int* in_sizes, int n_in,
                              void* d_out, int out_size)
{
    const float* x  = (const float*)d_in[0];
    const float* cw = (const float*)d_in[1];
    const float* cb = (const float*)d_in[2];
    float* out      = (float*)d_out;

    const int H = 256, W = 256;
    const int B = in_sizes[0] / (CCH * H * W);   // 16

    dim3 grid(W / TILE_W, H / TILE_H, B);        // (8, 32, 16) = 4096 blocks
    ho_fused_kernel<<<grid, NTHREADS>>>(x, cw, cb, out, H, W);
}

// round 4
// speedup vs baseline: 1.2450x; 1.2450x over previous
#include <cuda_runtime.h>

#define KS     5
#define TAPS   25
#define CCH    3
#define HALO   2
#define TILE_W 32
#define TILE_H 16          // each thread handles 2 vertically-adjacent pixels
#define SM_W   (TILE_W + 2*HALO)   // 36
#define SM_H   (TILE_H + 2*HALO)   // 20
#define NTHREADS 256

typedef unsigned long long u64;

__device__ __forceinline__ u64 pack2(float lo, float hi) {
    u64 r;
    asm("mov.b64 %0, {%1, %2};" : "=l"(r) : "f"(lo), "f"(hi));
    return r;
}
__device__ __forceinline__ void unpack2(u64 v, float& lo, float& hi) {
    asm("mov.b64 {%0, %1}, %2;" : "=f"(lo), "=f"(hi) : "l"(v));
}
__device__ __forceinline__ void ffma2(u64& d, u64 a, u64 b) {
    // packed 2xfp32 FMA: d = a*b + d  (Blackwell f32x2 path, full fp32 precision)
    asm("fma.rn.f32x2 %0, %1, %2, %0;" : "+l"(d) : "l"(a), "l"(b));
}

__global__ void __launch_bounds__(NTHREADS, 2)
ho_fused2_kernel(const float* __restrict__ x,
                 const float* __restrict__ cw,   // [25][3][5][5]
                 const float* __restrict__ cb,   // [25]
                 float* __restrict__ out,
                 int H, int W)
{
    __shared__ float s_tile[CCH][SM_H][SM_W];        // 2160 floats = 8.6 KB
    __shared__ u64   s_w2[TAPS * CCH * TAPS];        // weight duplicated in both lanes, 15 KB
    __shared__ u64   s_b2[TAPS];

    const int tid = threadIdx.x;

    // Stage weights duplicated into both f32x2 lanes (one LDS.64 per use later)
    for (int i = tid; i < TAPS * CCH * TAPS; i += NTHREADS) {
        float w = cw[i];
        s_w2[i] = pack2(w, w);
    }
    if (tid < TAPS) {
        float b = cb[tid];
        s_b2[tid] = pack2(b, b);
    }

    const int b  = blockIdx.z;
    const int h0 = blockIdx.y * TILE_H;
    const int w0 = blockIdx.x * TILE_W;
    const float* xb = x + (size_t)b * CCH * H * W;

    // Stage input tile + halo (zero-padded at borders)
    for (int i = tid; i < CCH * SM_H * SM_W; i += NTHREADS) {
        int c   = i / (SM_H * SM_W);
        int r   = (i / SM_W) % SM_H;
        int col = i % SM_W;
        int hh = h0 + r   - HALO;
        int ww = w0 + col - HALO;
        float v = 0.0f;
        if (hh >= 0 && hh < H && ww >= 0 && ww < W)
            v = xb[(size_t)c * H * W + (size_t)hh * W + ww];
        s_tile[c][r][col] = v;
    }
    __syncthreads();

    const int tx = tid & 31;          // 0..31
    const int ty = tid >> 5;          // 0..7
    const int ry = ty * 2;            // top pixel's tile-local row (halo space: +HALO)

    // ---- Pass 1: dynamic weights for BOTH pixels packed: wacc[k] = (w_k(p0), w_k(p1))
    u64 wacc[TAPS];
#pragma unroll
    for (int k = 0; k < TAPS; k++) wacc[k] = s_b2[k];

#pragma unroll
    for (int c = 0; c < CCH; c++) {
#pragma unroll
        for (int m = 0; m < TAPS; m++) {
            const int i = m / KS, j = m % KS;
            u64 nm = pack2(s_tile[c][ry + i][tx + j],
                           s_tile[c][ry + 1 + i][tx + j]);
#pragma unroll
            for (int k = 0; k < TAPS; k++)
                ffma2(wacc[k], s_w2[(k * CCH + c) * TAPS + m], nm);
        }
    }

    // ---- Pass 2: out[c] = x[c] + sum_m w_m * n[c][m], both pixels packed
    float* ob = out + (size_t)b * CCH * H * W;
    const int h = h0 + ry;
    const int w = w0 + tx;

#pragma unroll
    for (int c = 0; c < CCH; c++) {
        u64 acc = pack2(s_tile[c][ry + HALO][tx + HALO],
                        s_tile[c][ry + 1 + HALO][tx + HALO]);   // residual
#pragma unroll
        for (int m = 0; m < TAPS; m++) {
            const int i = m / KS, j = m % KS;
            u64 nm = pack2(s_tile[c][ry + i][tx + j],
                           s_tile[c][ry + 1 + i][tx + j]);
            ffma2(acc, wacc[m], nm);
        }
        float o0, o1;
        unpack2(acc, o0, o1);
        ob[(size_t)c * H * W + (size_t)h       * W + w] = o0;
        ob[(size_t)c * H * W + (size_t)(h + 1) * W + w] = o1;
    }
}

extern "C" void kernel_launch(void* const* d_in, const int* in_sizes, int n_in,
                              void* d_out, int out_size)
{
    const float* x  = (const float*)d_in[0];
    const float* cw = (const float*)d_in[1];
    const float* cb = (const float*)d_in[2];
    float* out      = (float*)d_out;

    const int H = 256, W = 256;
    const int B = in_sizes[0] / (CCH * H * W);   // 16

    dim3 grid(W / TILE_W, H / TILE_H, B);        // (8, 16, 16) = 2048 blocks
    ho_fused2_kernel<<<grid, NTHREADS>>>(x, cw, cb, out, H, W);
}

// round 6
// speedup vs baseline: 1.2644x; 1.0157x over previous
#include <cuda_runtime.h>

#define KS     5
#define TAPS   25
#define CCH    3
#define HALO   2
#define TILE_W 32
#define TILE_H 32          // each thread handles 4 vertically-adjacent pixels
#define RPT    4           // rows per thread
#define SM_W   (TILE_W + 2*HALO)   // 36
#define SM_H   (TILE_H + 2*HALO)   // 36
#define NTHREADS 256

typedef unsigned long long u64;

__device__ __forceinline__ u64 pack2(float lo, float hi) {
    u64 r;
    asm("mov.b64 %0, {%1, %2};" : "=l"(r) : "f"(lo), "f"(hi));
    return r;
}
__device__ __forceinline__ void unpack2(u64 v, float& lo, float& hi) {
    asm("mov.b64 {%0, %1}, %2;" : "=f"(lo), "=f"(hi) : "l"(v));
}
__device__ __forceinline__ void ffma2(u64& d, u64 a, u64 b) {
    asm("fma.rn.f32x2 %0, %1, %2, %0;" : "+l"(d) : "l"(a), "l"(b));
}

__global__ void __launch_bounds__(NTHREADS, 1)
ho_fused4_kernel(const float* __restrict__ x,
                 const float* __restrict__ cw,   // [25][3][5][5]
                 const float* __restrict__ cb,   // [25]
                 float* __restrict__ out,
                 int H, int W)
{
    __shared__ float s_tile[CCH][SM_H][SM_W];        // 3888 floats = 15.5 KB
    __shared__ u64   s_w2[TAPS * CCH * TAPS];        // weight dup'd in both lanes, 15 KB
    __shared__ u64   s_b2[TAPS];

    const int tid = threadIdx.x;

    for (int i = tid; i < TAPS * CCH * TAPS; i += NTHREADS) {
        float w = cw[i];
        s_w2[i] = pack2(w, w);
    }
    if (tid < TAPS) {
        float b = cb[tid];
        s_b2[tid] = pack2(b, b);
    }

    const int b  = blockIdx.z;
    const int h0 = blockIdx.y * TILE_H;
    const int w0 = blockIdx.x * TILE_W;
    const float* xb = x + (size_t)b * CCH * H * W;

    // Stage input tile + halo (zero-padded at borders)
    for (int i = tid; i < CCH * SM_H * SM_W; i += NTHREADS) {
        int c   = i / (SM_H * SM_W);
        int r   = (i / SM_W) % SM_H;
        int col = i % SM_W;
        int hh = h0 + r   - HALO;
        int ww = w0 + col - HALO;
        float v = 0.0f;
        if (hh >= 0 && hh < H && ww >= 0 && ww < W)
            v = xb[(size_t)c * H * W + (size_t)hh * W + ww];
        s_tile[c][r][col] = v;
    }
    __syncthreads();

    const int tx = tid & 31;          // 0..31
    const int ty = tid >> 5;          // 0..7
    const int ry = ty * RPT;          // top pixel's tile-local row (halo space: +HALO)

    // ---- Pass 1: dynamic weights for 4 pixels:
    //      waccA[k] = (w_k(row ry),   w_k(row ry+1))
    //      waccB[k] = (w_k(row ry+2), w_k(row ry+3))
    u64 waccA[TAPS], waccB[TAPS];
#pragma unroll
    for (int k = 0; k < TAPS; k++) { waccA[k] = s_b2[k]; waccB[k] = s_b2[k]; }

#pragma unroll
    for (int c = 0; c < CCH; c++) {
#pragma unroll
        for (int m = 0; m < TAPS; m++) {
            const int i = m / KS, j = m % KS;
            float n0 = s_tile[c][ry + i    ][tx + j];
            float n1 = s_tile[c][ry + i + 1][tx + j];
            float n2 = s_tile[c][ry + i + 2][tx + j];
            float n3 = s_tile[c][ry + i + 3][tx + j];
            u64 nmA = pack2(n0, n1);
            u64 nmB = pack2(n2, n3);
            const u64* wp = &s_w2[c * TAPS + m];     // stride TAPS*CCH over k
#pragma unroll
            for (int k = 0; k < TAPS; k++) {
                u64 wkv = wp[k * (CCH * TAPS)];      // one LDS.64, feeds 2 FFMA2
                ffma2(waccA[k], wkv, nmA);
                ffma2(waccB[k], wkv, nmB);
            }
        }
    }

    // ---- Pass 2: out[c] = x[c] + sum_m w_m * n[c][m], 4 pixels
    float* ob = out + (size_t)b * CCH * H * W;
    const int h = h0 + ry;
    const int w = w0 + tx;

#pragma unroll
    for (int c = 0; c < CCH; c++) {
        u64 accA = pack2(s_tile[c][ry + HALO    ][tx + HALO],
                         s_tile[c][ry + HALO + 1][tx + HALO]);   // residual rows 0,1
        u64 accB = pack2(s_tile[c][ry + HALO + 2][tx + HALO],
                         s_tile[c][ry + HALO + 3][tx + HALO]);   // residual rows 2,3
#pragma unroll
        for (int m = 0; m < TAPS; m++) {
            const int i = m / KS, j = m % KS;
            u64 nmA = pack2(s_tile[c][ry + i    ][tx + j],
                            s_tile[c][ry + i + 1][tx + j]);
            u64 nmB = pack2(s_tile[c][ry + i + 2][tx + j],
                            s_tile[c][ry + i + 3][tx + j]);
            ffma2(accA, waccA[m], nmA);
            ffma2(accB, waccB[m], nmB);
        }
        float o0, o1, o2, o3;
        unpack2(accA, o0, o1);
        unpack2(accB, o2, o3);
        float* op = ob + (size_t)c * H * W + (size_t)h * W + w;
        op[0 * W] = o0;
        op[1 * W] = o1;
        op[2 * W] = o2;
        op[3 * W] = o3;
    }
}

extern "C" void kernel_launch(void* const* d_in, const int* in_sizes, int n_in,
                              void* d_out, int out_size)
{
    const float* x  = (const float*)d_in[0];
    const float* cw = (const float*)d_in[1];
    const float* cb = (const float*)d_in[2];
    float* out      = (float*)d_out;

    const int H = 256, W = 256;
    const int B = in_sizes[0] / (CCH * H * W);   // 16

    dim3 grid(W / TILE_W, H / TILE_H, B);        // (8, 8, 16) = 1024 blocks
    ho_fused4_kernel<<<grid, NTHREADS>>>(x, cw, cb, out, H, W);
}